// round 16
// baseline (speedup 1.0000x reference)
#include <cuda_runtime.h>
#include <cstdint>
#include <mma.h>
#include <math.h>

using namespace nvcuda;

#define B_   4
#define T_   4096
#define D_   1024
#define H_   8
#define BS_  128
#define TB_  2048            /* timesteps per block (half of T) */
#define SC_  32              /* timesteps per GEMM sub-chunk */
#define NSC_ (TB_/SC_)       /* 64 */
#define NCB_ 32              /* channel-blocks: H * 4 quarters */
#define WP_  36              /* weight tile row stride */
#define ZPT_ 36              /* z tile (time-major) row stride */
#define XP_  132             /* x tile row stride */
#define ZBUF_ (SC_*ZPT_)     /* 1152 floats per z buffer */

// Scratch (device globals; no allocation allowed). No flags, no spins.
__device__ __align__(16) float g_ylocal[B_*T_*D_];   /* second half only */
__device__ __align__(16) float g_prefix[B_*T_*D_];
__device__ __align__(16) float g_S0[B_*D_];          /* state after first half */
__device__ __align__(16) float g_hP[B_*D_];          /* A-product of second half */
__device__ __align__(16) float g_hY[B_*D_];          /* local Y of second half */

// smem layout (floats)
#define OFF_W1   0
#define OFF_W2   (OFF_W1 + 128*WP_)     /* 4608  */
#define OFF_XS0  (OFF_W2 + 128*WP_)     /* 9216  */
#define OFF_XS1  (OFF_XS0 + SC_*XP_)    /* 13440 */
#define OFF_XS2  (OFF_XS1 + SC_*XP_)    /* 17664 */
#define OFF_Z1   (OFF_XS2 + SC_*XP_)    /* 21888: z1[2][32][ZPT_] */
#define OFF_Z2   (OFF_Z1 + 2*ZBUF_)     /* 24192: z2[2][32][ZPT_] */
#define OFF_SGA  (OFF_Z2 + 2*ZBUF_)     /* 26496: segA[8][32] */
#define OFF_SGY  (OFF_SGA + 8*32)       /* 26752 */
#define OFF_RUNA (OFF_SGY + 8*32)       /* 27008: runA[2][32] (parity) */
#define OFF_RUNY (OFF_RUNA + 2*32)      /* 27072 */
#define OFF_SPS  (OFF_RUNY + 2*32)      /* 27136 */
#define SMEM_FLOATS (OFF_SPS + 32)      /* 27168 -> 106.1 KB -> 2 CTAs/SM */
#define SMEM_BYTES  (SMEM_FLOATS*4)

__device__ __forceinline__ void cp16(unsigned dst, const float* src) {
    asm volatile("cp.async.cg.shared.global [%0], [%1], 16;" :: "r"(dst), "l"(src));
}
__device__ __forceinline__ float rsqrt_fast(float v) {
    float r; asm("rsqrt.approx.f32 %0, %1;" : "=f"(r) : "f"(v)); return r;
}

// ---------------------------------------------------------------------------
// K1: block = (gb time-half, channel-block, batch). 32 channels, 2048 steps.
// Pipelined: GEMM(cc+1) and scan(cc) share one inter-barrier region.
// Zero inter-block communication.
// ---------------------------------------------------------------------------
__global__ void __launch_bounds__(256, 2) k1_gemm_scan(
    const float* __restrict__ x, const float* __restrict__ a_param,
    const float* __restrict__ w_in, const float* __restrict__ w_a,
    float* __restrict__ out)
{
    extern __shared__ float sm[];
    float* w1s  = sm + OFF_W1;
    float* w2s  = sm + OFF_W2;
    float* z1   = sm + OFF_Z1;    // [2 buf][32 t][ZPT_] (time-major)
    float* z2   = sm + OFF_Z2;
    float* segA = sm + OFF_SGA;
    float* segY = sm + OFF_SGY;
    float* runA = sm + OFF_RUNA;  // [2][32] parity ping-pong
    float* runY = sm + OFF_RUNY;
    float* sps  = sm + OFF_SPS;

    const int b    = blockIdx.z;
    const int cb   = blockIdx.y;
    const int h    = cb >> 2;
    const int q    = cb & 3;
    const int gb   = blockIdx.x;          // 0 or 1
    const int tid  = threadIdx.x;
    const int col0 = h*BS_ + q*32;
    const int t0   = gb*TB_;

    // Stage weights (32 output cols of both gates), tf32 pre-rounded
    {
        const float* w1g = w_in + (size_t)h*BS_*BS_ + q*32;
        const float* w2g = w_a  + (size_t)h*BS_*BS_ + q*32;
        for (int i = tid; i < 128*32; i += 256) {
            int d = i >> 5, e = i & 31;
            w1s[d*WP_ + e] = wmma::__float_to_tf32(w1g[d*BS_ + e]);
            w2s[d*WP_ + e] = wmma::__float_to_tf32(w2g[d*BS_ + e]);
        }
        if (tid < 32) {
            float apv = a_param[col0 + tid];
            sps[tid]  = 8.0f * log1pf(__expf(apv));   // C * softplus(a_param)
            runA[tid] = 1.0f;  runA[32 + tid] = 1.0f;
            runY[tid] = 0.0f;  runY[32 + tid] = 0.0f;
        }
    }

    const int warp = tid >> 5;
    const int lane = tid & 31;            // lane == channel for scan phase
    // GEMM mapping
    const int g    = warp >> 2;        // gate 0/1
    const int rb   = (warp >> 1) & 1;  // 16-row (time) block of M=32
    const int cq   = warp & 1;         // 16-col half of N=32
    float* wg = g ? w2s : w1s;
    float* zgb = g ? z2 : z1;          // gate's z base (select buf at use site)

    const float* xg_base = x + ((size_t)(b*T_ + t0))*D_ + h*BS_;
    unsigned xsb[3];
    xsb[0] = (unsigned)__cvta_generic_to_shared(sm + OFF_XS0);
    xsb[1] = (unsigned)__cvta_generic_to_shared(sm + OFF_XS1);
    xsb[2] = (unsigned)__cvta_generic_to_shared(sm + OFF_XS2);
    float* xsf[3] = { sm + OFF_XS0, sm + OFF_XS1, sm + OFF_XS2 };

    __syncthreads();
    const float spe = sps[lane];

    // prolog: preload x(0) -> buf0 (group), x(1) -> buf1 (group)
    #pragma unroll
    for (int j = 0; j < 2; ++j) {
        const float* xg = xg_base + (size_t)j*SC_*D_;
        #pragma unroll
        for (int k = 0; k < 4; ++k) {
            int qq = tid + 256*k;
            int t  = qq >> 5, c4 = (qq & 31) << 2;
            cp16(xsb[j] + (unsigned)(t*XP_ + c4)*4u, xg + (size_t)t*D_ + c4);
        }
        asm volatile("cp.async.commit_group;");
    }
    asm volatile("cp.async.wait_group 1;");
    __syncthreads();   // x(0) visible

    // GEMM(0) -> z buf 0
    {
        wmma::fragment<wmma::accumulator, 16, 16, 8, float> acc;
        wmma::fill_fragment(acc, 0.0f);
        const float* xb = xsf[0] + rb*16*XP_;
        #pragma unroll 4
        for (int kk = 0; kk < 16; ++kk) {
            wmma::fragment<wmma::matrix_a, 16, 16, 8, wmma::precision::tf32, wmma::row_major> af;
            wmma::load_matrix_sync(af, xb + kk*8, XP_);
            wmma::fragment<wmma::matrix_b, 16, 16, 8, wmma::precision::tf32, wmma::row_major> bf;
            wmma::load_matrix_sync(bf, wg + kk*8*WP_ + cq*16, WP_);
            wmma::mma_sync(acc, af, bf, acc);
        }
        wmma::store_matrix_sync(zgb + (rb*16)*ZPT_ + cq*16, acc, ZPT_, wmma::mem_row_major);
    }

    for (int cc = 0; cc < NSC_; ++cc) {
        const int par = cc & 1;

        // commit x(cc+2) (or an empty group to keep the invariant uniform)
        if (cc + 2 < NSC_) {
            const float* xg = xg_base + (size_t)(cc+2)*SC_*D_;
            const unsigned dst = xsb[(cc+2)%3];
            #pragma unroll
            for (int k = 0; k < 4; ++k) {
                int qq = tid + 256*k;
                int t  = qq >> 5, c4 = (qq & 31) << 2;
                cp16(dst + (unsigned)(t*XP_ + c4)*4u, xg + (size_t)t*D_ + c4);
            }
        }
        asm volatile("cp.async.commit_group;");
        asm volatile("cp.async.wait_group 1;");   // x(cc+1) own-copies done
        __syncthreads();   // B1: z[par] (GEMM(cc)) + x(cc+1) visible; combine(cc-1) retired

        // ---- GEMM(cc+1) -> z[par^1]  (overlaps scan(cc) below) ----
        if (cc + 1 < NSC_) {
            wmma::fragment<wmma::accumulator, 16, 16, 8, float> acc;
            wmma::fill_fragment(acc, 0.0f);
            const float* xb = xsf[(cc+1)%3] + rb*16*XP_;
            #pragma unroll 4
            for (int kk = 0; kk < 16; ++kk) {
                wmma::fragment<wmma::matrix_a, 16, 16, 8, wmma::precision::tf32, wmma::row_major> af;
                wmma::load_matrix_sync(af, xb + kk*8, XP_);
                // no per-element CVT: tf32 MMA truncates fp32 mantissa (RZ on A)
                wmma::fragment<wmma::matrix_b, 16, 16, 8, wmma::precision::tf32, wmma::row_major> bf;
                wmma::load_matrix_sync(bf, wg + kk*8*WP_ + cq*16, WP_);
                wmma::mma_sync(acc, af, bf, acc);
            }
            wmma::store_matrix_sync(zgb + (par^1)*ZBUF_ + (rb*16)*ZPT_ + cq*16,
                                    acc, ZPT_, wmma::mem_row_major);
        }

        // ---- scan(cc) elementwise + segment summary (z[par], x[cc%3]) ----
        float av[4], bv[4];
        float Aseg = 1.0f, Yseg = 0.0f;
        {
            const float* z1b = z1 + par*ZBUF_;
            const float* z2b = z2 + par*ZBUF_;
            const float* xvb = xsf[cc%3];
            #pragma unroll
            for (int i = 0; i < 4; ++i) {
                const int t = warp*4 + i;
                float zx = z1b[t*ZPT_ + lane];
                float za = z2b[t*ZPT_ + lane];
                float gi = __fdividef(1.0f, 1.0f + __expf(-zx));
                float ga = __fdividef(1.0f, 1.0f + __expf(-za));
                float a  = __expf(-spe * ga);
                float m2 = fmaxf(fmaf(-a, a, 1.0f), 1e-30f);
                float mult = m2 * rsqrt_fast(m2);     // sqrt(m2)
                float xv = xvb[t*XP_ + q*32 + lane];
                float bb = mult * gi * xv;
                av[i] = a; bv[i] = bb;
                Yseg = fmaf(a, Yseg, bb);
                Aseg *= a;
            }
            segA[warp*32 + lane] = Aseg;
            segY[warp*32 + lane] = Yseg;
        }
        __syncthreads();   // B2: summaries visible (and GEMM(cc+1) z writes done)

        // ---- combine + coalesced stores (cc) ----
        {
            float Ar = runA[par*32 + lane];
            float Yr = runY[par*32 + lane];
            for (int s = 0; s < warp; ++s) {
                float As = segA[s*32 + lane];
                float Ys = segY[s*32 + lane];
                Yr = fmaf(As, Yr, Ys);
                Ar *= As;
            }
            if (warp == 7) {   // publish running state into other parity slot
                runY[(par^1)*32 + lane] = fmaf(Aseg, Yr, Yseg);
                runA[(par^1)*32 + lane] = Ar * Aseg;
            }

            float s = Yr;
            float P = Ar;
            const size_t gbase = ((size_t)(b*T_ + t0 + cc*SC_ + warp*4))*D_ + col0 + lane;
            if (gb == 0) {
                #pragma unroll
                for (int i = 0; i < 4; ++i) {
                    s = fmaf(av[i], s, bv[i]);
                    out[gbase + (size_t)i*D_] = s;    // carry-in is 0: y == local
                }
            } else {
                #pragma unroll
                for (int i = 0; i < 4; ++i) {
                    s = fmaf(av[i], s, bv[i]);
                    P *= av[i];
                    g_ylocal[gbase + (size_t)i*D_] = s;
                    g_prefix[gbase + (size_t)i*D_] = P;
                }
            }
        }
        // next iteration's B1 retires this combine
    }

    // fence warp 7's final parity-0 publish before reading it
    __syncthreads();

    // publish summaries (final running state is in parity NSC_&1 = 0)
    if (tid < 32) {
        const int gi  = b*D_ + col0 + tid;
        const int fin = (NSC_ & 1);
        if (gb == 0) {
            g_S0[gi] = runY[fin*32 + tid];
        } else {
            g_hP[gi] = runA[fin*32 + tid];
            g_hY[gi] = runY[fin*32 + tid];
        }
    }
}

// ---------------------------------------------------------------------------
// K2: h_last = A1 * S0 + Y1  (4096 channels)
// ---------------------------------------------------------------------------
__global__ void k2_hlast(float* __restrict__ out)
{
    int i = blockIdx.x*blockDim.x + threadIdx.x;   // 0 .. B*D-1
    out[(size_t)B_*T_*D_ + i] = fmaf(g_hP[i], g_S0[i], g_hY[i]);
}

// ---------------------------------------------------------------------------
// K3: second half only: y = y_local + S0 * prefix  (float4 streaming)
// ---------------------------------------------------------------------------
__global__ void __launch_bounds__(256) k3_apply(float* __restrict__ out)
{
    size_t j = (size_t)blockIdx.x*256 + threadIdx.x;   // over B*(T/2)*(D/4)
    int d4   = (int)(j & 255);                          // D/4 = 256
    size_t r = j >> 8;
    int t    = (int)(r & 2047) + TB_;                   // second half
    int b    = (int)(r >> 11);
    size_t i = ((size_t)(b*T_ + t))*D_ + d4*4;
    const float4 S  = *reinterpret_cast<const float4*>(g_S0 + b*D_ + d4*4);
    const float4 yl = *reinterpret_cast<const float4*>(g_ylocal + i);
    const float4 P  = *reinterpret_cast<const float4*>(g_prefix + i);
    float4 rr;
    rr.x = fmaf(S.x, P.x, yl.x);
    rr.y = fmaf(S.y, P.y, yl.y);
    rr.z = fmaf(S.z, P.z, yl.z);
    rr.w = fmaf(S.w, P.w, yl.w);
    *reinterpret_cast<float4*>(out + i) = rr;
}

extern "C" void kernel_launch(void* const* d_in, const int* in_sizes, int n_in,
                              void* d_out, int out_size)
{
    const float* x  = (const float*)d_in[0];
    const float* ap = (const float*)d_in[1];
    const float* wi = (const float*)d_in[2];
    const float* wa = (const float*)d_in[3];
    float* out = (float*)d_out;

    cudaFuncSetAttribute(k1_gemm_scan,
                         cudaFuncAttributeMaxDynamicSharedMemorySize, SMEM_BYTES);

    k1_gemm_scan<<<dim3(2, NCB_, B_), 256, SMEM_BYTES>>>(x, ap, wi, wa, out);
    k2_hlast<<<(B_*D_)/256, 256>>>(out);
    k3_apply<<<(B_*(T_/2)*(D_/4))/256, 256>>>(out);
}

// round 17
// speedup vs baseline: 1.1241x; 1.1241x over previous
#include <cuda_runtime.h>
#include <cstdint>
#include <mma.h>
#include <math.h>

using namespace nvcuda;

#define B_   4
#define T_   4096
#define D_   1024
#define H_   8
#define BS_  128
#define TB_  2048            /* timesteps per block (half of T) */
#define SC_  32              /* timesteps per GEMM sub-chunk */
#define NSC_ (TB_/SC_)       /* 64 */
#define NCB_ 32              /* channel-blocks: H * 4 quarters */
#define WPK_ 132             /* transposed weight tile row stride (K=128 +4) */
#define ZPT_ 36              /* z tile (time-major) row stride */
#define XP_  132             /* x tile row stride */

// Scratch (device globals; no allocation allowed). No flags, no spins.
__device__ __align__(16) float g_ylocal[B_*T_*D_];   /* second half only */
__device__ __align__(16) float g_prefix[B_*T_*D_];
__device__ __align__(16) float g_S0[B_*D_];          /* state after first half */
__device__ __align__(16) float g_hP[B_*D_];          /* A-product of second half */
__device__ __align__(16) float g_hY[B_*D_];          /* local Y of second half */

// smem layout (floats). Weights stored TRANSPOSED: wT[n][k], n=0..31, k=0..127
#define OFF_W1   0
#define OFF_W2   (OFF_W1 + 32*WPK_)     /* 4224  */
#define OFF_XS0  (OFF_W2 + 32*WPK_)     /* 8448  */
#define OFF_XS1  (OFF_XS0 + SC_*XP_)    /* 12672 */
#define OFF_Z1   (OFF_XS1 + SC_*XP_)    /* 16896 */
#define OFF_Z2   (OFF_Z1 + SC_*ZPT_)    /* 18048 */
#define OFF_SGA  (OFF_Z2 + SC_*ZPT_)    /* 19200: segA[8][32] */
#define OFF_SGY  (OFF_SGA + 8*32)       /* 19456 */
#define OFF_RUNA (OFF_SGY + 8*32)       /* 19712: runA[2][32] (parity) */
#define OFF_RUNY (OFF_RUNA + 2*32)      /* 19776 */
#define OFF_SPS  (OFF_RUNY + 2*32)      /* 19840 */
#define SMEM_FLOATS (OFF_SPS + 32)      /* 19872 -> 77.6 KB -> 2 CTAs/SM */
#define SMEM_BYTES  (SMEM_FLOATS*4)

__device__ __forceinline__ void cp16(unsigned dst, const float* src) {
    asm volatile("cp.async.cg.shared.global [%0], [%1], 16;" :: "r"(dst), "l"(src));
}
__device__ __forceinline__ float rsqrt_fast(float v) {
    float r; asm("rsqrt.approx.f32 %0, %1;" : "=f"(r) : "f"(v)); return r;
}
__device__ __forceinline__ void ldsm4(unsigned addr, unsigned &r0, unsigned &r1,
                                      unsigned &r2, unsigned &r3) {
    asm volatile("ldmatrix.sync.aligned.m8n8.x4.shared.b16 {%0,%1,%2,%3}, [%4];"
                 : "=r"(r0), "=r"(r1), "=r"(r2), "=r"(r3) : "r"(addr));
}
__device__ __forceinline__ void mma_tf32(float &d0, float &d1, float &d2, float &d3,
                                         unsigned a0, unsigned a1, unsigned a2, unsigned a3,
                                         unsigned b0, unsigned b1) {
    asm volatile("mma.sync.aligned.m16n8k8.row.col.f32.tf32.tf32.f32 "
                 "{%0,%1,%2,%3}, {%4,%5,%6,%7}, {%8,%9}, {%0,%1,%2,%3};"
                 : "+f"(d0), "+f"(d1), "+f"(d2), "+f"(d3)
                 : "r"(a0), "r"(a1), "r"(a2), "r"(a3), "r"(b0), "r"(b1));
}

// ---------------------------------------------------------------------------
// K1: block = (gb time-half, channel-block, batch). 32 channels, 2048 steps.
// GEMM via ldmatrix + mma.sync (m16n8k8 tf32). R15 phase structure.
// Zero inter-block communication.
// ---------------------------------------------------------------------------
__global__ void __launch_bounds__(256, 2) k1_gemm_scan(
    const float* __restrict__ x, const float* __restrict__ a_param,
    const float* __restrict__ w_in, const float* __restrict__ w_a,
    float* __restrict__ out)
{
    extern __shared__ float sm[];
    float* w1s  = sm + OFF_W1;    // wT[n][k] gate_x
    float* w2s  = sm + OFF_W2;    // wT[n][k] gate_a
    float* z1   = sm + OFF_Z1;    // [32 t][ZPT_] gate_x z (time-major)
    float* z2   = sm + OFF_Z2;    // [32 t][ZPT_] gate_a z
    float* segA = sm + OFF_SGA;
    float* segY = sm + OFF_SGY;
    float* runA = sm + OFF_RUNA;  // [2][32] parity ping-pong
    float* runY = sm + OFF_RUNY;
    float* sps  = sm + OFF_SPS;

    const int b    = blockIdx.z;
    const int cb   = blockIdx.y;
    const int h    = cb >> 2;
    const int q    = cb & 3;
    const int gb   = blockIdx.x;          // 0 or 1
    const int tid  = threadIdx.x;
    const int col0 = h*BS_ + q*32;
    const int t0   = gb*TB_;

    // Stage weights TRANSPOSED (wT[n][k]), tf32 pre-rounded
    {
        const float* w1g = w_in + (size_t)h*BS_*BS_ + q*32;
        const float* w2g = w_a  + (size_t)h*BS_*BS_ + q*32;
        for (int i = tid; i < 128*32; i += 256) {
            int n = i & 31, k = i >> 5;
            w1s[n*WPK_ + k] = wmma::__float_to_tf32(w1g[k*BS_ + n]);
            w2s[n*WPK_ + k] = wmma::__float_to_tf32(w2g[k*BS_ + n]);
        }
        if (tid < 32) {
            float apv = a_param[col0 + tid];
            sps[tid]  = 8.0f * log1pf(__expf(apv));   // C * softplus(a_param)
            runA[tid] = 1.0f;  runA[32 + tid] = 1.0f;
            runY[tid] = 0.0f;  runY[32 + tid] = 0.0f;
        }
    }

    const int warp = tid >> 5;
    const int lane = tid & 31;            // lane == channel for scan phase
    // GEMM mapping
    const int g    = warp >> 2;        // gate 0/1
    const int rb   = (warp >> 1) & 1;  // 16-row (time) block of M=32
    const int cq   = warp & 1;         // 16-col half of N=32
    float* zg = g ? z2 : z1;
    const unsigned wtb = (unsigned)__cvta_generic_to_shared(g ? w2s : w1s);

    const float* xg_base = x + ((size_t)(b*T_ + t0))*D_ + h*BS_;
    unsigned xsb[2];
    xsb[0] = (unsigned)__cvta_generic_to_shared(sm + OFF_XS0);
    xsb[1] = (unsigned)__cvta_generic_to_shared(sm + OFF_XS1);
    float* xsf[2] = { sm + OFF_XS0, sm + OFF_XS1 };

    // per-lane ldmatrix address components (constant across loop)
    const unsigned arow = (unsigned)(rb*16 + (lane & 7) + ((lane >> 3) & 1)*8);
    const unsigned acb  = (unsigned)(((lane >> 4) & 1) * 16);   // +16B = k cols 4-7
    const unsigned nrow = (unsigned)(cq*16 + (lane & 7) + ((lane >> 4) & 1)*8);
    const unsigned kcb  = (unsigned)(((lane >> 3) & 1) * 16);   // +16B = k cols 4-7
    const unsigned bbase = wtb + nrow*WPK_*4u + kcb;

    __syncthreads();
    const float spe = sps[lane];

    // preload tile 0 into buf 0
    {
        #pragma unroll
        for (int k = 0; k < 4; ++k) {
            int qq = tid + 256*k;
            int t  = qq >> 5, c4 = (qq & 31) << 2;
            cp16(xsb[0] + (unsigned)(t*XP_ + c4)*4u, xg_base + (size_t)t*D_ + c4);
        }
        asm volatile("cp.async.commit_group;");
    }

    for (int cc = 0; cc < NSC_; ++cc) {
        const int buf = cc & 1;
        const int par = cc & 1;
        const int ts  = cc*SC_;    // block-relative first timestep

        asm volatile("cp.async.wait_group 0;");
        __syncthreads();   // SA: x[buf] visible; prev scan fully retired

        // issue next tile into buf^1 (overlaps GEMM + scan below)
        if (cc + 1 < NSC_) {
            const float* xg = xg_base + (size_t)(ts + SC_)*D_;
            #pragma unroll
            for (int k = 0; k < 4; ++k) {
                int qq = tid + 256*k;
                int t  = qq >> 5, c4 = (qq & 31) << 2;
                cp16(xsb[buf^1] + (unsigned)(t*XP_ + c4)*4u, xg + (size_t)t*D_ + c4);
            }
            asm volatile("cp.async.commit_group;");
        }

        // ---- GEMM: M=32, N=32, K=128 via ldmatrix + mma.sync ----
        {
            float d[8] = {0.f,0.f,0.f,0.f,0.f,0.f,0.f,0.f};
            const unsigned abase = xsb[buf] + arow*XP_*4u + acb;
            #pragma unroll 4
            for (int kk = 0; kk < 16; ++kk) {
                unsigned a0,a1,a2,a3, b0,b1,b2,b3;
                ldsm4(abase + (unsigned)kk*32u, a0, a1, a2, a3);
                ldsm4(bbase + (unsigned)kk*32u, b0, b1, b2, b3);
                mma_tf32(d[0], d[1], d[2], d[3], a0, a1, a2, a3, b0, b1);
                mma_tf32(d[4], d[5], d[6], d[7], a0, a1, a2, a3, b2, b3);
            }
            // z store, time-major: row t = rb*16 + g2 (+8), col = cq*16 + nh*8 + tig*2
            const int g2 = lane >> 2, tig = lane & 3;
            float* zr = zg + (rb*16 + g2)*ZPT_ + cq*16 + tig*2;
            *reinterpret_cast<float2*>(zr)               = make_float2(d[0], d[1]);
            *reinterpret_cast<float2*>(zr + 8)           = make_float2(d[4], d[5]);
            *reinterpret_cast<float2*>(zr + 8*ZPT_)      = make_float2(d[2], d[3]);
            *reinterpret_cast<float2*>(zr + 8*ZPT_ + 8)  = make_float2(d[6], d[7]);
        }
        __syncthreads();   // SB: z visible

        // ---- elementwise + segment summary: warp = 4 timesteps, lane = ch ----
        float av[4], bv[4];
        float Aseg = 1.0f, Yseg = 0.0f;
        {
            #pragma unroll
            for (int i = 0; i < 4; ++i) {
                const int t = warp*4 + i;
                float zx = z1[t*ZPT_ + lane];
                float za = z2[t*ZPT_ + lane];
                float gi = __fdividef(1.0f, 1.0f + __expf(-zx));
                float ga = __fdividef(1.0f, 1.0f + __expf(-za));
                float a  = __expf(-spe * ga);
                float m2 = fmaxf(fmaf(-a, a, 1.0f), 1e-30f);
                float mult = m2 * rsqrt_fast(m2);     // sqrt(m2)
                float xv = xsf[buf][t*XP_ + q*32 + lane];
                float bb = mult * gi * xv;
                av[i] = a; bv[i] = bb;
                Yseg = fmaf(a, Yseg, bb);
                Aseg *= a;
            }
            segA[warp*32 + lane] = Aseg;
            segY[warp*32 + lane] = Yseg;
        }
        __syncthreads();   // SC: summaries visible

        // ---- per-warp combine of preceding segments + coalesced stores ----
        {
            float Ar = runA[par*32 + lane];
            float Yr = runY[par*32 + lane];
            for (int s = 0; s < warp; ++s) {
                float As = segA[s*32 + lane];
                float Ys = segY[s*32 + lane];
                Yr = fmaf(As, Yr, Ys);
                Ar *= As;
            }
            if (warp == 7) {   // publish running state into other parity slot
                runY[(par^1)*32 + lane] = fmaf(Aseg, Yr, Yseg);
                runA[(par^1)*32 + lane] = Ar * Aseg;
            }

            float s = Yr;
            float P = Ar;
            const size_t gbase = ((size_t)(b*T_ + t0 + ts + warp*4))*D_ + col0 + lane;
            if (gb == 0) {
                #pragma unroll
                for (int i = 0; i < 4; ++i) {
                    s = fmaf(av[i], s, bv[i]);
                    out[gbase + (size_t)i*D_] = s;    // carry-in is 0: y == local
                }
            } else {
                #pragma unroll
                for (int i = 0; i < 4; ++i) {
                    s = fmaf(av[i], s, bv[i]);
                    P *= av[i];
                    g_ylocal[gbase + (size_t)i*D_] = s;
                    g_prefix[gbase + (size_t)i*D_] = P;
                }
            }
        }
        // no trailing sync: next iteration's SA barrier retires this scan
    }

    // fence warp 7's final parity-0 publish before reading it
    __syncthreads();

    // publish summaries (final running state is in parity NSC_&1 = 0)
    if (tid < 32) {
        const int gi  = b*D_ + col0 + tid;
        const int fin = (NSC_ & 1);
        if (gb == 0) {
            g_S0[gi] = runY[fin*32 + tid];
        } else {
            g_hP[gi] = runA[fin*32 + tid];
            g_hY[gi] = runY[fin*32 + tid];
        }
    }
}

// ---------------------------------------------------------------------------
// K2: h_last = A1 * S0 + Y1  (4096 channels)
// ---------------------------------------------------------------------------
__global__ void k2_hlast(float* __restrict__ out)
{
    int i = blockIdx.x*blockDim.x + threadIdx.x;   // 0 .. B*D-1
    out[(size_t)B_*T_*D_ + i] = fmaf(g_hP[i], g_S0[i], g_hY[i]);
}

// ---------------------------------------------------------------------------
// K3: second half only: y = y_local + S0 * prefix  (float4 streaming)
// ---------------------------------------------------------------------------
__global__ void __launch_bounds__(256) k3_apply(float* __restrict__ out)
{
    size_t j = (size_t)blockIdx.x*256 + threadIdx.x;   // over B*(T/2)*(D/4)
    int d4   = (int)(j & 255);                          // D/4 = 256
    size_t r = j >> 8;
    int t    = (int)(r & 2047) + TB_;                   // second half
    int b    = (int)(r >> 11);
    size_t i = ((size_t)(b*T_ + t))*D_ + d4*4;
    const float4 S  = *reinterpret_cast<const float4*>(g_S0 + b*D_ + d4*4);
    const float4 yl = *reinterpret_cast<const float4*>(g_ylocal + i);
    const float4 P  = *reinterpret_cast<const float4*>(g_prefix + i);
    float4 rr;
    rr.x = fmaf(S.x, P.x, yl.x);
    rr.y = fmaf(S.y, P.y, yl.y);
    rr.z = fmaf(S.z, P.z, yl.z);
    rr.w = fmaf(S.w, P.w, yl.w);
    *reinterpret_cast<float4*>(out + i) = rr;
}

extern "C" void kernel_launch(void* const* d_in, const int* in_sizes, int n_in,
                              void* d_out, int out_size)
{
    const float* x  = (const float*)d_in[0];
    const float* ap = (const float*)d_in[1];
    const float* wi = (const float*)d_in[2];
    const float* wa = (const float*)d_in[3];
    float* out = (float*)d_out;

    cudaFuncSetAttribute(k1_gemm_scan,
                         cudaFuncAttributeMaxDynamicSharedMemorySize, SMEM_BYTES);

    k1_gemm_scan<<<dim3(2, NCB_, B_), 256, SMEM_BYTES>>>(x, ap, wi, wa, out);
    k2_hlast<<<(B_*D_)/256, 256>>>(out);
    k3_apply<<<(B_*(T_/2)*(D_/4))/256, 256>>>(out);
}